// round 15
// baseline (speedup 1.0000x reference)
#include <cuda_runtime.h>
#include <cuda_fp16.h>
#include <cuda_bf16.h>
#include <cstdint>

#define MAX_N   100000
#define MAX_E   1600000
#define IN_DIM  128
#define HID     64

typedef unsigned long long ull;

// ---------------- device scratch ----------------
__device__ __align__(128) __half2 g_t[MAX_N * 32]; // messages fp16 (128B/row)
__device__ float g_h[MAX_N * HID];        // activations (fp32)
__device__ float g_dinv[MAX_N];           // deg^{-1/2} (incl self loop)
__device__ int   g_deg[MAX_N];            // edge-only in-degree
__device__ int   g_rowstart[MAX_N];       // CSR segment starts (unordered layout)
__device__ int   g_fill[MAX_N];           // scatter cursors
__device__ int   g_col[MAX_E];            // CSR column (src), grouped by dst
__device__ int   g_total;                 // segment allocator
__device__ int   g_is64;                  // edge_index dtype flag

// ---------------- tf32 helpers ----------------
__device__ __forceinline__ uint32_t to_tf32(float f) {
    uint32_t u;
    asm("cvt.rna.tf32.f32 %0,%1;" : "=r"(u) : "f"(f));
    return u;
}
__device__ __forceinline__ void mma_tf32(float& d0, float& d1, float& d2, float& d3,
                                         uint32_t a0, uint32_t a1, uint32_t a2, uint32_t a3,
                                         uint32_t b0, uint32_t b1) {
    asm("mma.sync.aligned.m16n8k8.row.col.f32.tf32.tf32.f32 "
        "{%0,%1,%2,%3},{%4,%5,%6,%7},{%8,%9},{%0,%1,%2,%3};"
        : "+f"(d0), "+f"(d1), "+f"(d2), "+f"(d3)
        : "r"(a0), "r"(a1), "r"(a2), "r"(a3), "r"(b0), "r"(b1));
}

// ---------------- detect dtype + zero deg/total (fused) ----------------
__global__ void k_detect_init(const void* ei, int e, int n) {
    int i = blockIdx.x * blockDim.x + threadIdx.x;
    if (i < n) g_deg[i] = 0;
    if (i == 0) g_total = 0;
    if (blockIdx.x == 0) {
        __shared__ int bad;
        if (threadIdx.x == 0) bad = 0;
        __syncthreads();
        const long long* p = (const long long*)ei;
        int samples = e < 2048 ? e : 2048;
        long long stride = e / samples; if (stride < 1) stride = 1;
        for (int j = threadIdx.x; j < samples; j += blockDim.x) {
            long long idx = (long long)j * stride;
            if (idx < e) {
                long long v = p[idx];
                if (v < 0 || v >= n) bad = 1;
            }
        }
        __syncthreads();
        if (threadIdx.x == 0) g_is64 = bad ? 0 : 1;
    }
}

// ---------------- degree count ----------------
__global__ void k_count(const void* ei, int e) {
    int i = blockIdx.x * blockDim.x + threadIdx.x;
    if (i >= e) return;
    int d;
    if (g_is64) d = (int)((const long long*)ei)[e + i];
    else        d = ((const int*)ei)[e + i];
    atomicAdd(&g_deg[d], 1);
}

// ---------------- segment assignment + dinv (warp-aggregated atomic) ------
__global__ void k_rows(int n) {
    int i = blockIdx.x * blockDim.x + threadIdx.x;
    int lane = threadIdx.x & 31;
    int d = (i < n) ? g_deg[i] : 0;
    if (i < n) g_dinv[i] = rsqrtf((float)(d + 1));
    int incl = d;
    #pragma unroll
    for (int off = 1; off < 32; off <<= 1) {
        int v = __shfl_up_sync(0xffffffffu, incl, off);
        if (lane >= off) incl += v;
    }
    int warpsum = __shfl_sync(0xffffffffu, incl, 31);
    int base = 0;
    if (lane == 0 && warpsum > 0) base = atomicAdd(&g_total, warpsum);
    base = __shfl_sync(0xffffffffu, base, 0);
    int start = base + incl - d;
    if (i < n) {
        g_rowstart[i] = start;
        g_fill[i] = start;
    }
}

// ---------------- scatter edges into CSR ----------------
__global__ void k_scatter(const void* ei, int e) {
    int i = blockIdx.x * blockDim.x + threadIdx.x;
    if (i >= e) return;
    int s, d;
    if (g_is64) {
        const long long* p = (const long long*)ei;
        s = (int)p[i]; d = (int)p[e + i];
    } else {
        const int* p = (const int*)ei;
        s = p[i]; d = p[e + i];
    }
    int pos = atomicAdd(&g_fill[d], 1);
    g_col[pos] = s;
}

// ---------------- GEMM v5: tf32 mma.m16n8k8, fp16 output ------------------
// out[r,:] = half( (A[r,:K] @ W[K,64]) * dinv[r] )
template <int K>
__global__ __launch_bounds__(256) void k_gemm(const float* __restrict__ A,
                                              const float* __restrict__ W,
                                              __half2* __restrict__ out, int n) {
    __shared__ uint32_t As[128 * 64];   // 32 KB, tf32 bits
    __shared__ uint32_t Ws[64 * 64];    // 16 KB, tf32 bits
    int tid = threadIdx.x;
    int lane = tid & 31;
    int w = tid >> 5;
    int rr = lane >> 2;                 // 0..7
    int c4 = lane & 3;                  // 0..3
    int row0 = blockIdx.x * 128;

    float acc[8][4];
    #pragma unroll
    for (int nt = 0; nt < 8; ++nt)
        #pragma unroll
        for (int j = 0; j < 4; ++j) acc[nt][j] = 0.f;

    #pragma unroll
    for (int kc = 0; kc < K; kc += 64) {
        #pragma unroll
        for (int i = 0; i < 4; ++i) {
            int f = tid + i * 256;
            int k = f >> 4;
            int nf = (f & 15) * 4;
            const float4 v = *(const float4*)(W + (size_t)(kc + k) * 64 + nf);
            uint4 u;
            u.x = to_tf32(v.x); u.y = to_tf32(v.y);
            u.z = to_tf32(v.z); u.w = to_tf32(v.w);
            *(uint4*)&Ws[k * 64 + (nf ^ ((k & 3) << 3))] = u;
        }
        #pragma unroll
        for (int i = 0; i < 8; ++i) {
            int f = tid + i * 256;
            int r = f >> 4;
            int kk = (f & 15) * 4;
            int gr = row0 + r;
            float4 v = make_float4(0.f, 0.f, 0.f, 0.f);
            if (gr < n) v = *(const float4*)(A + (size_t)gr * K + kc + kk);
            uint4 u;
            u.x = to_tf32(v.x); u.y = to_tf32(v.y);
            u.z = to_tf32(v.z); u.w = to_tf32(v.w);
            *(uint4*)&As[r * 64 + (kk ^ ((r & 7) << 2))] = u;
        }
        __syncthreads();

        int rsw = rr << 2;
        const uint32_t* Ar0 = &As[(w * 16 + rr) * 64];
        const uint32_t* Ar1 = Ar0 + 8 * 64;
        #pragma unroll
        for (int ks = 0; ks < 8; ++ks) {
            int k0 = ks * 8 + c4;
            uint32_t a0 = Ar0[k0 ^ rsw];
            uint32_t a1 = Ar1[k0 ^ rsw];
            uint32_t a2 = Ar0[(k0 + 4) ^ rsw];
            uint32_t a3 = Ar1[(k0 + 4) ^ rsw];
            const uint32_t* Wk0 = &Ws[k0 * 64];
            const uint32_t* Wk1 = &Ws[(k0 + 4) * 64];
            #pragma unroll
            for (int nt = 0; nt < 8; ++nt) {
                int np = (nt * 8 + rr) ^ (c4 << 3);
                mma_tf32(acc[nt][0], acc[nt][1], acc[nt][2], acc[nt][3],
                         a0, a1, a2, a3, Wk0[np], Wk1[np]);
            }
        }
        __syncthreads();
    }

    int r0 = row0 + w * 16 + rr;
    int r1 = r0 + 8;
    if (r0 < n) {
        float di = g_dinv[r0];
        #pragma unroll
        for (int nt = 0; nt < 8; ++nt)
            out[(size_t)r0 * 32 + nt * 4 + c4] =
                __floats2half2_rn(acc[nt][0] * di, acc[nt][1] * di);
    }
    if (r1 < n) {
        float di = g_dinv[r1];
        #pragma unroll
        for (int nt = 0; nt < 8; ++nt)
            out[(size_t)r1 * 32 + nt * 4 + c4] =
                __floats2half2_rn(acc[nt][2] * di, acc[nt][3] * di);
    }
}

// ---------------- CSR aggregation: persistent, warp/node, fp16 msgs -------
// h[i] = relu( b + dinv_i * ( t[i] + sum_{s in in(i)} t[s] ) )
__global__ __launch_bounds__(256) void k_agg(const __half2* __restrict__ t,
                                             const float* __restrict__ b,
                                             float* __restrict__ hout, int n) {
    int tid = threadIdx.x;
    int lane = tid & 31;
    int gw = (blockIdx.x * 256 + tid) >> 5;
    int nw = (gridDim.x * 256) >> 5;
    float bx = b[2 * lane], by = b[2 * lane + 1];
    for (int i = gw; i < n; i += nw) {
        float2 a0 = __half22float2(t[(size_t)i * 32 + lane]);   // self term
        float2 a1 = make_float2(0.f, 0.f);
        int s0 = g_rowstart[i];
        int s1 = s0 + g_deg[i];
        int idx = s0;
        for (; idx + 3 < s1; idx += 4) {
            int c0 = g_col[idx],     c1 = g_col[idx + 1];
            int c2 = g_col[idx + 2], c3 = g_col[idx + 3];
            __half2 v0 = t[(size_t)c0 * 32 + lane];
            __half2 v1 = t[(size_t)c1 * 32 + lane];
            __half2 v2 = t[(size_t)c2 * 32 + lane];
            __half2 v3 = t[(size_t)c3 * 32 + lane];
            float2 f0 = __half22float2(v0);
            float2 f1 = __half22float2(v1);
            float2 f2 = __half22float2(v2);
            float2 f3 = __half22float2(v3);
            a0.x += f0.x; a0.y += f0.y;
            a1.x += f1.x; a1.y += f1.y;
            a0.x += f2.x; a0.y += f2.y;
            a1.x += f3.x; a1.y += f3.y;
        }
        for (; idx < s1; ++idx) {
            int c = g_col[idx];
            float2 f = __half22float2(t[(size_t)c * 32 + lane]);
            a0.x += f.x; a0.y += f.y;
        }
        float sx = a0.x + a1.x;
        float sy = a0.y + a1.y;
        float di = g_dinv[i];
        float2 o;
        o.x = fmaxf(fmaf(di, sx, bx), 0.f);
        o.y = fmaxf(fmaf(di, sy, by), 0.f);
        ((float2*)hout)[(size_t)i * 32 + lane] = o;
    }
}

// ---------------- layer-3 agg fused with MLP head -------------------------
__global__ __launch_bounds__(256) void k_agg_mlp(const __half2* __restrict__ t,
                                                 const float* __restrict__ b3,
                                                 const float* __restrict__ Wp1,
                                                 const float* __restrict__ bp1,
                                                 const float* __restrict__ Wp2,
                                                 const float* __restrict__ bp2,
                                                 float* __restrict__ out, int n) {
    __shared__ float W1s[64 * 32];
    __shared__ float W2s[32];
    int tid = threadIdx.x;
    for (int i = tid; i < 64 * 32; i += 256) W1s[i] = Wp1[i];
    if (tid < 32) W2s[tid] = Wp2[tid];
    __syncthreads();
    int lane = tid & 31;
    int gw = (blockIdx.x * 256 + tid) >> 5;
    int nw = (gridDim.x * 256) >> 5;
    float bx = b3[2 * lane], by = b3[2 * lane + 1];
    float bb = bp1[lane];
    float w2v = W2s[lane];
    float b2v = bp2[0];
    for (int i = gw; i < n; i += nw) {
        float2 a0 = __half22float2(t[(size_t)i * 32 + lane]);
        float2 a1 = make_float2(0.f, 0.f);
        int s0 = g_rowstart[i];
        int s1 = s0 + g_deg[i];
        int idx = s0;
        for (; idx + 3 < s1; idx += 4) {
            int c0 = g_col[idx],     c1 = g_col[idx + 1];
            int c2 = g_col[idx + 2], c3 = g_col[idx + 3];
            __half2 v0 = t[(size_t)c0 * 32 + lane];
            __half2 v1 = t[(size_t)c1 * 32 + lane];
            __half2 v2 = t[(size_t)c2 * 32 + lane];
            __half2 v3 = t[(size_t)c3 * 32 + lane];
            float2 f0 = __half22float2(v0);
            float2 f1 = __half22float2(v1);
            float2 f2 = __half22float2(v2);
            float2 f3 = __half22float2(v3);
            a0.x += f0.x; a0.y += f0.y;
            a1.x += f1.x; a1.y += f1.y;
            a0.x += f2.x; a0.y += f2.y;
            a1.x += f3.x; a1.y += f3.y;
        }
        for (; idx < s1; ++idx) {
            int c = g_col[idx];
            float2 f = __half22float2(t[(size_t)c * 32 + lane]);
            a0.x += f.x; a0.y += f.y;
        }
        float sx = a0.x + a1.x;
        float sy = a0.y + a1.y;
        float di = g_dinv[i];
        float hx = fmaxf(fmaf(di, sx, bx), 0.f);   // h3[2*lane]
        float hy = fmaxf(fmaf(di, sy, by), 0.f);   // h3[2*lane+1]
        float acc = 0.f;
        #pragma unroll
        for (int k = 0; k < 32; ++k) {
            float vx = __shfl_sync(0xffffffffu, hx, k);
            float vy = __shfl_sync(0xffffffffu, hy, k);
            acc = fmaf(vx, W1s[(2 * k) * 32 + lane], acc);
            acc = fmaf(vy, W1s[(2 * k + 1) * 32 + lane], acc);
        }
        float z = fmaxf(acc + bb, 0.f);
        float p = z * w2v;
        #pragma unroll
        for (int o2 = 16; o2 > 0; o2 >>= 1) p += __shfl_xor_sync(0xffffffffu, p, o2);
        if (lane == 0) out[i] = p + b2v;
    }
}

// ---------------- launch ----------------
extern "C" void kernel_launch(void* const* d_in, const int* in_sizes, int n_in,
                              void* d_out, int out_size) {
    const float* x   = (const float*)d_in[0];
    const void*  ei  = d_in[1];
    const float* W1  = (const float*)d_in[3];
    const float* b1  = (const float*)d_in[4];
    const float* W2  = (const float*)d_in[5];
    const float* b2  = (const float*)d_in[6];
    const float* W3  = (const float*)d_in[7];
    const float* b3  = (const float*)d_in[8];
    const float* Wp1 = (const float*)d_in[9];
    const float* bp1 = (const float*)d_in[10];
    const float* Wp2 = (const float*)d_in[11];
    const float* bp2 = (const float*)d_in[12];
    float* out = (float*)d_out;

    int n = in_sizes[0] / IN_DIM;
    int e = in_sizes[1] / 2;

    __half2* t = nullptr; float* h = nullptr;
    cudaGetSymbolAddress((void**)&t, g_t);
    cudaGetSymbolAddress((void**)&h, g_h);

    int nb_n = (n + 255) / 256;
    int nb_e = (e + 255) / 256;
    int nb_g = (n + 127) / 128;      // gemm tiles (128 rows)
    int nb_p = 1184;                 // persistent grids (148 SMs x 8 CTAs)

    // --- preprocessing (serial; gemm1 only needs dinv, scatter after) ---
    k_detect_init<<<nb_n, 256>>>(ei, e, n);       // #1
    k_count<<<nb_e, 256>>>(ei, e);                // #2
    k_rows<<<nb_n, 256>>>(n);                     // #3

    // --- layer 1 GEMM as launch #4 (ncu capture anchor) ---
    k_gemm<IN_DIM><<<nb_g, 256>>>(x, W1, t, n);   // #4
    k_scatter<<<nb_e, 256>>>(ei, e);              // #5 (before agg1)

    // --- layer 1 agg, layer 2, layer 3 agg fused with MLP ---
    k_agg<<<nb_p, 256>>>(t, b1, h, n);
    k_gemm<HID><<<nb_g, 256>>>(h, W2, t, n);
    k_agg<<<nb_p, 256>>>(t, b2, h, n);
    k_gemm<HID><<<nb_g, 256>>>(h, W3, t, n);
    k_agg_mlp<<<nb_p, 256>>>(t, b3, Wp1, bp1, Wp2, bp2, out, n);
}

// round 16
// speedup vs baseline: 1.0262x; 1.0262x over previous
#include <cuda_runtime.h>
#include <cuda_bf16.h>
#include <cstdint>

#define MAX_N   100000
#define MAX_E   1600000
#define IN_DIM  128
#define HID     64

typedef unsigned long long ull;

// ---------------- device scratch ----------------
__device__ float g_t[MAX_N * HID];        // GEMM output (dinv-scaled)
__device__ float g_h[MAX_N * HID];        // activations
__device__ float g_dinv[MAX_N];           // deg^{-1/2} (incl self loop)
__device__ int   g_deg[MAX_N];            // edge-only in-degree
__device__ int   g_rowstart[MAX_N];       // CSR segment starts (unordered layout)
__device__ int   g_fill[MAX_N];           // scatter cursors
__device__ int   g_col[MAX_E];            // CSR column (src), grouped by dst
__device__ int   g_total;                 // segment allocator
__device__ int   g_is64;                  // edge_index dtype flag

// ---------------- f32x2 helpers ----------------
__device__ __forceinline__ ull add2(ull a, ull b) {
    ull d;
    asm("add.rn.f32x2 %0,%1,%2;" : "=l"(d) : "l"(a), "l"(b));
    return d;
}
__device__ __forceinline__ float2 unpack2(ull v) {
    float2 r;
    asm("mov.b64 {%0,%1},%2;" : "=f"(r.x), "=f"(r.y) : "l"(v));
    return r;
}

// ---------------- tf32 helpers ----------------
__device__ __forceinline__ uint32_t to_tf32(float f) {
    uint32_t u;
    asm("cvt.rna.tf32.f32 %0,%1;" : "=r"(u) : "f"(f));
    return u;
}
__device__ __forceinline__ void mma_tf32(float& d0, float& d1, float& d2, float& d3,
                                         uint32_t a0, uint32_t a1, uint32_t a2, uint32_t a3,
                                         uint32_t b0, uint32_t b1) {
    asm("mma.sync.aligned.m16n8k8.row.col.f32.tf32.tf32.f32 "
        "{%0,%1,%2,%3},{%4,%5,%6,%7},{%8,%9},{%0,%1,%2,%3};"
        : "+f"(d0), "+f"(d1), "+f"(d2), "+f"(d3)
        : "r"(a0), "r"(a1), "r"(a2), "r"(a3), "r"(b0), "r"(b1));
}

// ---------------- detect dtype + zero deg/total (fused) ----------------
__global__ void k_detect_init(const void* ei, int e, int n) {
    int i = blockIdx.x * blockDim.x + threadIdx.x;
    if (i < n) g_deg[i] = 0;
    if (i == 0) g_total = 0;
    if (blockIdx.x == 0) {
        __shared__ int bad;
        if (threadIdx.x == 0) bad = 0;
        __syncthreads();
        const long long* p = (const long long*)ei;
        int samples = e < 2048 ? e : 2048;
        long long stride = e / samples; if (stride < 1) stride = 1;
        for (int j = threadIdx.x; j < samples; j += blockDim.x) {
            long long idx = (long long)j * stride;
            if (idx < e) {
                long long v = p[idx];
                if (v < 0 || v >= n) bad = 1;
            }
        }
        __syncthreads();
        if (threadIdx.x == 0) g_is64 = bad ? 0 : 1;
    }
}

// ---------------- degree count ----------------
__global__ void k_count(const void* ei, int e) {
    int i = blockIdx.x * blockDim.x + threadIdx.x;
    if (i >= e) return;
    int d;
    if (g_is64) d = (int)((const long long*)ei)[e + i];
    else        d = ((const int*)ei)[e + i];
    atomicAdd(&g_deg[d], 1);
}

// ---------------- segment assignment + dinv (warp-aggregated atomic) ------
__global__ void k_rows(int n) {
    int i = blockIdx.x * blockDim.x + threadIdx.x;
    int lane = threadIdx.x & 31;
    int d = (i < n) ? g_deg[i] : 0;
    if (i < n) g_dinv[i] = rsqrtf((float)(d + 1));
    int incl = d;
    #pragma unroll
    for (int off = 1; off < 32; off <<= 1) {
        int v = __shfl_up_sync(0xffffffffu, incl, off);
        if (lane >= off) incl += v;
    }
    int warpsum = __shfl_sync(0xffffffffu, incl, 31);
    int base = 0;
    if (lane == 0 && warpsum > 0) base = atomicAdd(&g_total, warpsum);
    base = __shfl_sync(0xffffffffu, base, 0);
    int start = base + incl - d;
    if (i < n) {
        g_rowstart[i] = start;
        g_fill[i] = start;
    }
}

// ---------------- scatter edges into CSR ----------------
__global__ void k_scatter(const void* ei, int e) {
    int i = blockIdx.x * blockDim.x + threadIdx.x;
    if (i >= e) return;
    int s, d;
    if (g_is64) {
        const long long* p = (const long long*)ei;
        s = (int)p[i]; d = (int)p[e + i];
    } else {
        const int* p = (const int*)ei;
        s = p[i]; d = p[e + i];
    }
    int pos = atomicAdd(&g_fill[d], 1);
    g_col[pos] = s;
}

// ---------------- GEMM v6: tf32 mma, single tile, single sync -------------
// out[r,:] = (A[r,:K] @ W[K,64]) * dinv[r]
// Dynamic smem: As[128*K] + Ws[K*64] (tf32 bits). One fill phase (high MLP),
// one __syncthreads, one straight K-loop of MMAs. Swizzles as v5.
template <int K>
__global__ __launch_bounds__(256) void k_gemm(const float* __restrict__ A,
                                              const float* __restrict__ W,
                                              float* __restrict__ out, int n) {
    extern __shared__ uint32_t smem[];
    uint32_t* As = smem;             // 128 rows x K
    uint32_t* Ws = smem + 128 * K;   // K x 64
    int tid = threadIdx.x;
    int lane = tid & 31;
    int w = tid >> 5;
    int rr = lane >> 2;                 // 0..7
    int c4 = lane & 3;                  // 0..3
    int row0 = blockIdx.x * 128;

    // --- fill W [K x 64] : K*16 float4 total ---
    #pragma unroll
    for (int i = 0; i < K / 16; ++i) {
        int f = tid + i * 256;
        int k = f >> 4;
        int nf = (f & 15) * 4;
        const float4 v = *(const float4*)(W + (size_t)k * 64 + nf);
        uint4 u;
        u.x = to_tf32(v.x); u.y = to_tf32(v.y);
        u.z = to_tf32(v.z); u.w = to_tf32(v.w);
        *(uint4*)&Ws[k * 64 + (nf ^ ((k & 3) << 3))] = u;
    }
    // --- fill A [128 x K] : 32*K float4 total ---
    #pragma unroll
    for (int i = 0; i < K / 8; ++i) {
        int f = tid + i * 256;
        int r = f / (K / 4);
        int kk = (f % (K / 4)) * 4;
        int gr = row0 + r;
        float4 v = make_float4(0.f, 0.f, 0.f, 0.f);
        if (gr < n) v = *(const float4*)(A + (size_t)gr * K + kk);
        uint4 u;
        u.x = to_tf32(v.x); u.y = to_tf32(v.y);
        u.z = to_tf32(v.z); u.w = to_tf32(v.w);
        *(uint4*)&As[r * K + (kk ^ ((r & 7) << 2))] = u;
    }
    __syncthreads();

    float acc[8][4];
    #pragma unroll
    for (int nt = 0; nt < 8; ++nt)
        #pragma unroll
        for (int j = 0; j < 4; ++j) acc[nt][j] = 0.f;

    int rsw = rr << 2;
    const uint32_t* Ar0 = &As[(w * 16 + rr) * K];
    const uint32_t* Ar1 = Ar0 + 8 * K;
    #pragma unroll
    for (int ks = 0; ks < K / 8; ++ks) {
        int k0 = ks * 8 + c4;
        uint32_t a0 = Ar0[k0 ^ rsw];
        uint32_t a1 = Ar1[k0 ^ rsw];
        uint32_t a2 = Ar0[(k0 + 4) ^ rsw];
        uint32_t a3 = Ar1[(k0 + 4) ^ rsw];
        const uint32_t* Wk0 = &Ws[k0 * 64];
        const uint32_t* Wk1 = &Ws[(k0 + 4) * 64];
        #pragma unroll
        for (int nt = 0; nt < 8; ++nt) {
            int np = (nt * 8 + rr) ^ (c4 << 3);
            mma_tf32(acc[nt][0], acc[nt][1], acc[nt][2], acc[nt][3],
                     a0, a1, a2, a3, Wk0[np], Wk1[np]);
        }
    }

    int r0 = row0 + w * 16 + rr;
    int r1 = r0 + 8;
    if (r0 < n) {
        float di = g_dinv[r0];
        #pragma unroll
        for (int nt = 0; nt < 8; ++nt) {
            float2 o; o.x = acc[nt][0] * di; o.y = acc[nt][1] * di;
            *(float2*)(out + (size_t)r0 * 64 + nt * 8 + c4 * 2) = o;
        }
    }
    if (r1 < n) {
        float di = g_dinv[r1];
        #pragma unroll
        for (int nt = 0; nt < 8; ++nt) {
            float2 o; o.x = acc[nt][2] * di; o.y = acc[nt][3] * di;
            *(float2*)(out + (size_t)r1 * 64 + nt * 8 + c4 * 2) = o;
        }
    }
}

// ---------------- CSR aggregation (R14 exact): persistent, warp/node ------
// h[i] = relu( b + dinv_i * ( t[i] + sum_{s in in(i)} t[s] ) )
__global__ __launch_bounds__(256) void k_agg(const float* __restrict__ t,
                                             const float* __restrict__ b,
                                             float* __restrict__ hout, int n) {
    int tid = threadIdx.x;
    int lane = tid & 31;
    int gw = (blockIdx.x * 256 + tid) >> 5;
    int nw = (gridDim.x * 256) >> 5;
    const ull* __restrict__ t8 = (const ull*)t;
    float bx = b[2 * lane], by = b[2 * lane + 1];
    for (int i = gw; i < n; i += nw) {
        ull acc0 = t8[(size_t)i * 32 + lane];  // self term
        ull acc1 = 0ull;
        int s0 = g_rowstart[i];
        int s1 = s0 + g_deg[i];
        int idx = s0;
        for (; idx + 3 < s1; idx += 4) {
            int c0 = g_col[idx],     c1 = g_col[idx + 1];
            int c2 = g_col[idx + 2], c3 = g_col[idx + 3];
            ull v0 = t8[(size_t)c0 * 32 + lane];
            ull v1 = t8[(size_t)c1 * 32 + lane];
            ull v2 = t8[(size_t)c2 * 32 + lane];
            ull v3 = t8[(size_t)c3 * 32 + lane];
            acc0 = add2(acc0, v0);
            acc1 = add2(acc1, v1);
            acc0 = add2(acc0, v2);
            acc1 = add2(acc1, v3);
        }
        for (; idx < s1; ++idx) {
            int c = g_col[idx];
            acc0 = add2(acc0, t8[(size_t)c * 32 + lane]);
        }
        float2 s = unpack2(add2(acc0, acc1));
        float di = g_dinv[i];
        float2 o;
        o.x = fmaxf(fmaf(di, s.x, bx), 0.f);
        o.y = fmaxf(fmaf(di, s.y, by), 0.f);
        ((float2*)hout)[(size_t)i * 32 + lane] = o;
    }
}

// ---------------- layer-3 agg fused with MLP head -------------------------
__global__ __launch_bounds__(256) void k_agg_mlp(const float* __restrict__ t,
                                                 const float* __restrict__ b3,
                                                 const float* __restrict__ Wp1,
                                                 const float* __restrict__ bp1,
                                                 const float* __restrict__ Wp2,
                                                 const float* __restrict__ bp2,
                                                 float* __restrict__ out, int n) {
    __shared__ float W1s[64 * 32];
    __shared__ float W2s[32];
    int tid = threadIdx.x;
    for (int i = tid; i < 64 * 32; i += 256) W1s[i] = Wp1[i];
    if (tid < 32) W2s[tid] = Wp2[tid];
    __syncthreads();
    int lane = tid & 31;
    int gw = (blockIdx.x * 256 + tid) >> 5;
    int nw = (gridDim.x * 256) >> 5;
    const ull* __restrict__ t8 = (const ull*)t;
    float bx = b3[2 * lane], by = b3[2 * lane + 1];
    float bb = bp1[lane];
    float w2v = W2s[lane];
    float b2v = bp2[0];
    for (int i = gw; i < n; i += nw) {
        ull acc0 = t8[(size_t)i * 32 + lane];
        ull acc1 = 0ull;
        int s0 = g_rowstart[i];
        int s1 = s0 + g_deg[i];
        int idx = s0;
        for (; idx + 3 < s1; idx += 4) {
            int c0 = g_col[idx],     c1 = g_col[idx + 1];
            int c2 = g_col[idx + 2], c3 = g_col[idx + 3];
            ull v0 = t8[(size_t)c0 * 32 + lane];
            ull v1 = t8[(size_t)c1 * 32 + lane];
            ull v2 = t8[(size_t)c2 * 32 + lane];
            ull v3 = t8[(size_t)c3 * 32 + lane];
            acc0 = add2(acc0, v0);
            acc1 = add2(acc1, v1);
            acc0 = add2(acc0, v2);
            acc1 = add2(acc1, v3);
        }
        for (; idx < s1; ++idx) {
            int c = g_col[idx];
            acc0 = add2(acc0, t8[(size_t)c * 32 + lane]);
        }
        float2 s = unpack2(add2(acc0, acc1));
        float di = g_dinv[i];
        float hx = fmaxf(fmaf(di, s.x, bx), 0.f);   // h3[2*lane]
        float hy = fmaxf(fmaf(di, s.y, by), 0.f);   // h3[2*lane+1]
        float acc = 0.f;
        #pragma unroll
        for (int k = 0; k < 32; ++k) {
            float vx = __shfl_sync(0xffffffffu, hx, k);
            float vy = __shfl_sync(0xffffffffu, hy, k);
            acc = fmaf(vx, W1s[(2 * k) * 32 + lane], acc);
            acc = fmaf(vy, W1s[(2 * k + 1) * 32 + lane], acc);
        }
        float z = fmaxf(acc + bb, 0.f);
        float p = z * w2v;
        #pragma unroll
        for (int o2 = 16; o2 > 0; o2 >>= 1) p += __shfl_xor_sync(0xffffffffu, p, o2);
        if (lane == 0) out[i] = p + b2v;
    }
}

// ---------------- launch ----------------
extern "C" void kernel_launch(void* const* d_in, const int* in_sizes, int n_in,
                              void* d_out, int out_size) {
    const float* x   = (const float*)d_in[0];
    const void*  ei  = d_in[1];
    const float* W1  = (const float*)d_in[3];
    const float* b1  = (const float*)d_in[4];
    const float* W2  = (const float*)d_in[5];
    const float* b2  = (const float*)d_in[6];
    const float* W3  = (const float*)d_in[7];
    const float* b3  = (const float*)d_in[8];
    const float* Wp1 = (const float*)d_in[9];
    const float* bp1 = (const float*)d_in[10];
    const float* Wp2 = (const float*)d_in[11];
    const float* bp2 = (const float*)d_in[12];
    float* out = (float*)d_out;

    int n = in_sizes[0] / IN_DIM;
    int e = in_sizes[1] / 2;

    float* t = nullptr; float* h = nullptr;
    cudaGetSymbolAddress((void**)&t, g_t);
    cudaGetSymbolAddress((void**)&h, g_h);

    int nb_n = (n + 255) / 256;
    int nb_e = (e + 255) / 256;
    int nb_g = (n + 127) / 128;      // gemm tiles (128 rows)
    int nb_p = 1184;                 // persistent grids (148 SMs x 8 CTAs)

    // dynamic smem: As[128*K] + Ws[K*64] tf32 words
    const int smem128 = (128 * 128 + 128 * 64) * 4;   // 96 KB
    const int smem64  = (128 * 64 + 64 * 64) * 4;     // 48 KB
    cudaFuncSetAttribute(k_gemm<IN_DIM>,
                         cudaFuncAttributeMaxDynamicSharedMemorySize, smem128);
    cudaFuncSetAttribute(k_gemm<HID>,
                         cudaFuncAttributeMaxDynamicSharedMemorySize, smem64);

    // --- preprocessing (serial; gemm1 only needs dinv, scatter after) ---
    k_detect_init<<<nb_n, 256>>>(ei, e, n);               // #1
    k_count<<<nb_e, 256>>>(ei, e);                        // #2
    k_rows<<<nb_n, 256>>>(n);                             // #3

    // --- layer 1 GEMM as launch #4 (ncu capture anchor) ---
    k_gemm<IN_DIM><<<nb_g, 256, smem128>>>(x, W1, t, n);  // #4
    k_scatter<<<nb_e, 256>>>(ei, e);                      // #5 (before agg1)

    // --- layer 1 agg, layer 2, layer 3 agg fused with MLP ---
    k_agg<<<nb_p, 256>>>(t, b1, h, n);
    k_gemm<HID><<<nb_g, 256, smem64>>>(h, W2, t, n);
    k_agg<<<nb_p, 256>>>(t, b2, h, n);
    k_gemm<HID><<<nb_g, 256, smem64>>>(h, W3, t, n);
    k_agg_mlp<<<nb_p, 256>>>(t, b3, Wp1, bp1, Wp2, bp2, out, n);
}

// round 17
// speedup vs baseline: 1.0294x; 1.0032x over previous
#include <cuda_runtime.h>
#include <cuda_bf16.h>
#include <cstdint>

#define MAX_N   100000
#define MAX_E   1600000
#define IN_DIM  128
#define HID     64

typedef unsigned long long ull;

// ---------------- device scratch ----------------
__device__ float g_t[MAX_N * HID];        // GEMM output (dinv-scaled)
__device__ float g_h[MAX_N * HID];        // activations
__device__ float g_dinv[MAX_N];           // deg^{-1/2} (incl self loop)
__device__ int   g_deg[MAX_N];            // edge-only in-degree
__device__ int   g_rowstart[MAX_N];       // CSR segment starts (unordered layout)
__device__ int   g_rank[MAX_E];           // within-node edge rank (from count)
__device__ int   g_col[MAX_E];            // CSR column (src), grouped by dst
__device__ int   g_total;                 // segment allocator
__device__ int   g_is64;                  // edge_index dtype flag

// ---------------- f32x2 helpers ----------------
__device__ __forceinline__ ull add2(ull a, ull b) {
    ull d;
    asm("add.rn.f32x2 %0,%1,%2;" : "=l"(d) : "l"(a), "l"(b));
    return d;
}
__device__ __forceinline__ float2 unpack2(ull v) {
    float2 r;
    asm("mov.b64 {%0,%1},%2;" : "=f"(r.x), "=f"(r.y) : "l"(v));
    return r;
}

// ---------------- tf32 helpers ----------------
__device__ __forceinline__ uint32_t to_tf32(float f) {
    uint32_t u;
    asm("cvt.rna.tf32.f32 %0,%1;" : "=r"(u) : "f"(f));
    return u;
}
__device__ __forceinline__ void mma_tf32(float& d0, float& d1, float& d2, float& d3,
                                         uint32_t a0, uint32_t a1, uint32_t a2, uint32_t a3,
                                         uint32_t b0, uint32_t b1) {
    asm("mma.sync.aligned.m16n8k8.row.col.f32.tf32.tf32.f32 "
        "{%0,%1,%2,%3},{%4,%5,%6,%7},{%8,%9},{%0,%1,%2,%3};"
        : "+f"(d0), "+f"(d1), "+f"(d2), "+f"(d3)
        : "r"(a0), "r"(a1), "r"(a2), "r"(a3), "r"(b0), "r"(b1));
}

// ---------------- detect dtype + zero deg/total (fused) ----------------
__global__ void k_detect_init(const void* ei, int e, int n) {
    int i = blockIdx.x * blockDim.x + threadIdx.x;
    if (i < n) g_deg[i] = 0;
    if (i == 0) g_total = 0;
    if (blockIdx.x == 0) {
        __shared__ int bad;
        if (threadIdx.x == 0) bad = 0;
        __syncthreads();
        const long long* p = (const long long*)ei;
        int samples = e < 2048 ? e : 2048;
        long long stride = e / samples; if (stride < 1) stride = 1;
        for (int j = threadIdx.x; j < samples; j += blockDim.x) {
            long long idx = (long long)j * stride;
            if (idx < e) {
                long long v = p[idx];
                if (v < 0 || v >= n) bad = 1;
            }
        }
        __syncthreads();
        if (threadIdx.x == 0) g_is64 = bad ? 0 : 1;
    }
}

// ---------------- degree count + rank recording ----------------
__global__ void k_count(const void* ei, int e) {
    int i = blockIdx.x * blockDim.x + threadIdx.x;
    if (i >= e) return;
    int d;
    if (g_is64) d = (int)((const long long*)ei)[e + i];
    else        d = ((const int*)ei)[e + i];
    g_rank[i] = atomicAdd(&g_deg[d], 1);
}

// ---------------- segment assignment + dinv (warp-aggregated atomic) ------
__global__ void k_rows(int n) {
    int i = blockIdx.x * blockDim.x + threadIdx.x;
    int lane = threadIdx.x & 31;
    int d = (i < n) ? g_deg[i] : 0;
    if (i < n) g_dinv[i] = rsqrtf((float)(d + 1));
    int incl = d;
    #pragma unroll
    for (int off = 1; off < 32; off <<= 1) {
        int v = __shfl_up_sync(0xffffffffu, incl, off);
        if (lane >= off) incl += v;
    }
    int warpsum = __shfl_sync(0xffffffffu, incl, 31);
    int base = 0;
    if (lane == 0 && warpsum > 0) base = atomicAdd(&g_total, warpsum);
    base = __shfl_sync(0xffffffffu, base, 0);
    int start = base + incl - d;
    if (i < n) g_rowstart[i] = start;
}

// ---------------- scatter edges into CSR (atomic-free) ----------------
__global__ void k_scatter(const void* ei, int e) {
    int i = blockIdx.x * blockDim.x + threadIdx.x;
    if (i >= e) return;
    int s, d;
    if (g_is64) {
        const long long* p = (const long long*)ei;
        s = (int)p[i]; d = (int)p[e + i];
    } else {
        const int* p = (const int*)ei;
        s = p[i]; d = p[e + i];
    }
    g_col[g_rowstart[d] + g_rank[i]] = s;
}

// ---------------- GEMM v6: tf32 mma, single tile, single sync -------------
// out[r,:] = (A[r,:K] @ W[K,64]) * dinv[r]
template <int K>
__global__ __launch_bounds__(256) void k_gemm(const float* __restrict__ A,
                                              const float* __restrict__ W,
                                              float* __restrict__ out, int n) {
    extern __shared__ uint32_t smem[];
    uint32_t* As = smem;             // 128 rows x K
    uint32_t* Ws = smem + 128 * K;   // K x 64
    int tid = threadIdx.x;
    int lane = tid & 31;
    int w = tid >> 5;
    int rr = lane >> 2;                 // 0..7
    int c4 = lane & 3;                  // 0..3
    int row0 = blockIdx.x * 128;

    // --- fill W [K x 64] ---
    #pragma unroll
    for (int i = 0; i < K / 16; ++i) {
        int f = tid + i * 256;
        int k = f >> 4;
        int nf = (f & 15) * 4;
        const float4 v = *(const float4*)(W + (size_t)k * 64 + nf);
        uint4 u;
        u.x = to_tf32(v.x); u.y = to_tf32(v.y);
        u.z = to_tf32(v.z); u.w = to_tf32(v.w);
        *(uint4*)&Ws[k * 64 + (nf ^ ((k & 3) << 3))] = u;
    }
    // --- fill A [128 x K] ---
    #pragma unroll
    for (int i = 0; i < K / 8; ++i) {
        int f = tid + i * 256;
        int r = f / (K / 4);
        int kk = (f % (K / 4)) * 4;
        int gr = row0 + r;
        float4 v = make_float4(0.f, 0.f, 0.f, 0.f);
        if (gr < n) v = *(const float4*)(A + (size_t)gr * K + kk);
        uint4 u;
        u.x = to_tf32(v.x); u.y = to_tf32(v.y);
        u.z = to_tf32(v.z); u.w = to_tf32(v.w);
        *(uint4*)&As[r * K + (kk ^ ((r & 7) << 2))] = u;
    }
    __syncthreads();

    float acc[8][4];
    #pragma unroll
    for (int nt = 0; nt < 8; ++nt)
        #pragma unroll
        for (int j = 0; j < 4; ++j) acc[nt][j] = 0.f;

    int rsw = rr << 2;
    const uint32_t* Ar0 = &As[(w * 16 + rr) * K];
    const uint32_t* Ar1 = Ar0 + 8 * K;
    #pragma unroll
    for (int ks = 0; ks < K / 8; ++ks) {
        int k0 = ks * 8 + c4;
        uint32_t a0 = Ar0[k0 ^ rsw];
        uint32_t a1 = Ar1[k0 ^ rsw];
        uint32_t a2 = Ar0[(k0 + 4) ^ rsw];
        uint32_t a3 = Ar1[(k0 + 4) ^ rsw];
        const uint32_t* Wk0 = &Ws[k0 * 64];
        const uint32_t* Wk1 = &Ws[(k0 + 4) * 64];
        #pragma unroll
        for (int nt = 0; nt < 8; ++nt) {
            int np = (nt * 8 + rr) ^ (c4 << 3);
            mma_tf32(acc[nt][0], acc[nt][1], acc[nt][2], acc[nt][3],
                     a0, a1, a2, a3, Wk0[np], Wk1[np]);
        }
    }

    int r0 = row0 + w * 16 + rr;
    int r1 = r0 + 8;
    if (r0 < n) {
        float di = g_dinv[r0];
        #pragma unroll
        for (int nt = 0; nt < 8; ++nt) {
            float2 o; o.x = acc[nt][0] * di; o.y = acc[nt][1] * di;
            *(float2*)(out + (size_t)r0 * 64 + nt * 8 + c4 * 2) = o;
        }
    }
    if (r1 < n) {
        float di = g_dinv[r1];
        #pragma unroll
        for (int nt = 0; nt < 8; ++nt) {
            float2 o; o.x = acc[nt][2] * di; o.y = acc[nt][3] * di;
            *(float2*)(out + (size_t)r1 * 64 + nt * 8 + c4 * 2) = o;
        }
    }
}

// ---------------- CSR aggregation: persistent, warp/node ------------------
// h[i] = relu( b + dinv_i * ( t[i] + sum_{s in in(i)} t[s] ) )
__global__ __launch_bounds__(256) void k_agg(const float* __restrict__ t,
                                             const float* __restrict__ b,
                                             float* __restrict__ hout, int n) {
    int tid = threadIdx.x;
    int lane = tid & 31;
    int gw = (blockIdx.x * 256 + tid) >> 5;
    int nw = (gridDim.x * 256) >> 5;
    const ull* __restrict__ t8 = (const ull*)t;
    float bx = b[2 * lane], by = b[2 * lane + 1];
    for (int i = gw; i < n; i += nw) {
        ull acc0 = t8[(size_t)i * 32 + lane];  // self term
        ull acc1 = 0ull;
        int s0 = g_rowstart[i];
        int s1 = s0 + g_deg[i];
        int idx = s0;
        for (; idx + 3 < s1; idx += 4) {
            int c0 = g_col[idx],     c1 = g_col[idx + 1];
            int c2 = g_col[idx + 2], c3 = g_col[idx + 3];
            ull v0 = t8[(size_t)c0 * 32 + lane];
            ull v1 = t8[(size_t)c1 * 32 + lane];
            ull v2 = t8[(size_t)c2 * 32 + lane];
            ull v3 = t8[(size_t)c3 * 32 + lane];
            acc0 = add2(acc0, v0);
            acc1 = add2(acc1, v1);
            acc0 = add2(acc0, v2);
            acc1 = add2(acc1, v3);
        }
        for (; idx < s1; ++idx) {
            int c = g_col[idx];
            acc0 = add2(acc0, t8[(size_t)c * 32 + lane]);
        }
        float2 s = unpack2(add2(acc0, acc1));
        float di = g_dinv[i];
        float2 o;
        o.x = fmaxf(fmaf(di, s.x, bx), 0.f);
        o.y = fmaxf(fmaf(di, s.y, by), 0.f);
        ((float2*)hout)[(size_t)i * 32 + lane] = o;
    }
}

// ---------------- layer-3 agg fused with MLP head -------------------------
__global__ __launch_bounds__(256) void k_agg_mlp(const float* __restrict__ t,
                                                 const float* __restrict__ b3,
                                                 const float* __restrict__ Wp1,
                                                 const float* __restrict__ bp1,
                                                 const float* __restrict__ Wp2,
                                                 const float* __restrict__ bp2,
                                                 float* __restrict__ out, int n) {
    __shared__ float W1s[64 * 32];
    __shared__ float W2s[32];
    int tid = threadIdx.x;
    for (int i = tid; i < 64 * 32; i += 256) W1s[i] = Wp1[i];
    if (tid < 32) W2s[tid] = Wp2[tid];
    __syncthreads();
    int lane = tid & 31;
    int gw = (blockIdx.x * 256 + tid) >> 5;
    int nw = (gridDim.x * 256) >> 5;
    const ull* __restrict__ t8 = (const ull*)t;
    float bx = b3[2 * lane], by = b3[2 * lane + 1];
    float bb = bp1[lane];
    float w2v = W2s[lane];
    float b2v = bp2[0];
    for (int i = gw; i < n; i += nw) {
        ull acc0 = t8[(size_t)i * 32 + lane];
        ull acc1 = 0ull;
        int s0 = g_rowstart[i];
        int s1 = s0 + g_deg[i];
        int idx = s0;
        for (; idx + 3 < s1; idx += 4) {
            int c0 = g_col[idx],     c1 = g_col[idx + 1];
            int c2 = g_col[idx + 2], c3 = g_col[idx + 3];
            ull v0 = t8[(size_t)c0 * 32 + lane];
            ull v1 = t8[(size_t)c1 * 32 + lane];
            ull v2 = t8[(size_t)c2 * 32 + lane];
            ull v3 = t8[(size_t)c3 * 32 + lane];
            acc0 = add2(acc0, v0);
            acc1 = add2(acc1, v1);
            acc0 = add2(acc0, v2);
            acc1 = add2(acc1, v3);
        }
        for (; idx < s1; ++idx) {
            int c = g_col[idx];
            acc0 = add2(acc0, t8[(size_t)c * 32 + lane]);
        }
        float2 s = unpack2(add2(acc0, acc1));
        float di = g_dinv[i];
        float hx = fmaxf(fmaf(di, s.x, bx), 0.f);   // h3[2*lane]
        float hy = fmaxf(fmaf(di, s.y, by), 0.f);   // h3[2*lane+1]
        float acc = 0.f;
        #pragma unroll
        for (int k = 0; k < 32; ++k) {
            float vx = __shfl_sync(0xffffffffu, hx, k);
            float vy = __shfl_sync(0xffffffffu, hy, k);
            acc = fmaf(vx, W1s[(2 * k) * 32 + lane], acc);
            acc = fmaf(vy, W1s[(2 * k + 1) * 32 + lane], acc);
        }
        float z = fmaxf(acc + bb, 0.f);
        float p = z * w2v;
        #pragma unroll
        for (int o2 = 16; o2 > 0; o2 >>= 1) p += __shfl_xor_sync(0xffffffffu, p, o2);
        if (lane == 0) out[i] = p + b2v;
    }
}

// ---------------- launch ----------------
extern "C" void kernel_launch(void* const* d_in, const int* in_sizes, int n_in,
                              void* d_out, int out_size) {
    const float* x   = (const float*)d_in[0];
    const void*  ei  = d_in[1];
    const float* W1  = (const float*)d_in[3];
    const float* b1  = (const float*)d_in[4];
    const float* W2  = (const float*)d_in[5];
    const float* b2  = (const float*)d_in[6];
    const float* W3  = (const float*)d_in[7];
    const float* b3  = (const float*)d_in[8];
    const float* Wp1 = (const float*)d_in[9];
    const float* bp1 = (const float*)d_in[10];
    const float* Wp2 = (const float*)d_in[11];
    const float* bp2 = (const float*)d_in[12];
    float* out = (float*)d_out;

    int n = in_sizes[0] / IN_DIM;
    int e = in_sizes[1] / 2;

    float* t = nullptr; float* h = nullptr;
    cudaGetSymbolAddress((void**)&t, g_t);
    cudaGetSymbolAddress((void**)&h, g_h);

    int nb_n = (n + 255) / 256;
    int nb_e = (e + 255) / 256;
    int nb_g = (n + 127) / 128;      // gemm tiles (128 rows)
    int nb_p = 1184;                 // persistent grids (148 SMs x 8 CTAs)

    const int smem128 = (128 * 128 + 128 * 64) * 4;   // 96 KB
    const int smem64  = (128 * 64 + 64 * 64) * 4;     // 48 KB
    cudaFuncSetAttribute(k_gemm<IN_DIM>,
                         cudaFuncAttributeMaxDynamicSharedMemorySize, smem128);
    cudaFuncSetAttribute(k_gemm<HID>,
                         cudaFuncAttributeMaxDynamicSharedMemorySize, smem64);

    // --- preprocessing (serial; gemm1 only needs dinv, scatter after) ---
    k_detect_init<<<nb_n, 256>>>(ei, e, n);               // #1
    k_count<<<nb_e, 256>>>(ei, e);                        // #2 (records rank)
    k_rows<<<nb_n, 256>>>(n);                             // #3

    // --- layer 1 GEMM as launch #4 (ncu capture anchor) ---
    k_gemm<IN_DIM><<<nb_g, 256, smem128>>>(x, W1, t, n);  // #4
    k_scatter<<<nb_e, 256>>>(ei, e);                      // #5 (atomic-free)

    // --- layer 1 agg, layer 2, layer 3 agg fused with MLP ---
    k_agg<<<nb_p, 256>>>(t, b1, h, n);
    k_gemm<HID><<<nb_g, 256, smem64>>>(h, W2, t, n);
    k_agg<<<nb_p, 256>>>(t, b2, h, n);
    k_gemm<HID><<<nb_g, 256, smem64>>>(h, W3, t, n);
    k_agg_mlp<<<nb_p, 256>>>(t, b3, Wp1, bp1, Wp2, bp2, out, n);
}